// round 10
// baseline (speedup 1.0000x reference)
#include <cuda_runtime.h>
#include <cuda_fp16.h>

// WaterLevelLSTM via mma.sync.m16n8k16 (f16 -> f32), single-term fp16 h,
// MUFU.TANH activations. R10: 32 batch rows per warp (two m16 tiles served
// sequentially by ONE B-fragment load) -> W-table + bias LDS traffic per row
// halves. 1 CTA x 320 threads (10 warps, reg cap 204) to avoid R8's spill.

#define TSTEPS 5
#define NTH    320
#define MT     320           // batch rows per CTA (10 warps x 32)
#define ROWPAD 72            // halves per row (144B) -> ldsm conflict-free

// smem byte offsets
#define SM_WHI  0            // 256*72*2 = 36864
#define SM_A    36864        // 10 warps x 4608 (two m16 tiles of h fp16)
#define SM_BC   82944        // [8 jg][4 tig][4 float4] = 2048 (bias+wih)
#define SM_WFC  84992        // 64 floats
#define SM_X    85248        // 320*5 floats = 6400
#define SM_SIZE 91648

typedef unsigned int u32;

__device__ __forceinline__ void mma16816(float* d, const u32* a, const u32* b) {
    asm volatile("mma.sync.aligned.m16n8k16.row.col.f32.f16.f16.f32 "
        "{%0,%1,%2,%3}, {%4,%5,%6,%7}, {%8,%9}, {%0,%1,%2,%3};"
        : "+f"(d[0]), "+f"(d[1]), "+f"(d[2]), "+f"(d[3])
        : "r"(a[0]), "r"(a[1]), "r"(a[2]), "r"(a[3]), "r"(b[0]), "r"(b[1]));
}
__device__ __forceinline__ void ldsm4(u32* r, u32 addr) {
    asm volatile("ldmatrix.sync.aligned.m8n8.x4.shared.b16 {%0,%1,%2,%3}, [%4];"
        : "=r"(r[0]), "=r"(r[1]), "=r"(r[2]), "=r"(r[3]) : "r"(addr));
}
__device__ __forceinline__ u32 s2u(const void* p) {
    u32 a;
    asm("{ .reg .u64 t; cvta.to.shared.u64 t, %1; cvt.u32.u64 %0, t; }"
        : "=r"(a) : "l"(p));
    return a;
}
__device__ __forceinline__ u32 packh2(float a, float b) {
    __half2 h = __floats2half2_rn(a, b);
    return *reinterpret_cast<u32*>(&h);
}
__device__ __forceinline__ void sts32(u32 addr, u32 v) {
    asm volatile("st.shared.b32 [%0], %1;" :: "r"(addr), "r"(v) : "memory");
}
// hardware tanh (MUFU.TANH): 1 MUFU op
__device__ __forceinline__ float tanh_hw(float x) {
    float r;
    asm("tanh.approx.f32 %0, %1;" : "=f"(r) : "f"(x));
    return r;
}
__device__ __forceinline__ float sigf(float x) {
    return fmaf(tanh_hw(0.5f * x), 0.5f, 0.5f);
}

__global__ __launch_bounds__(NTH, 1)
void lstm_mma_kernel(const float* __restrict__ x,
                     const float* __restrict__ W_ih,
                     const float* __restrict__ W_hh,
                     const float* __restrict__ b_ih,
                     const float* __restrict__ b_hh,
                     const float* __restrict__ W_fc,
                     const float* __restrict__ b_fc,
                     float* __restrict__ out,
                     int B)
{
    extern __shared__ char smem[];
    const u32 sb = s2u(smem);
    const int tid  = threadIdx.x;
    const int warp = tid >> 5;
    const int lane = tid & 31;
    const int gid  = lane >> 2;      // row group in m16 tile
    const int tig  = lane & 3;       // col group

    __half* whi   = reinterpret_cast<__half*>(smem + SM_WHI);
    float*  bc_s  = reinterpret_cast<float*>(smem + SM_BC);
    float*  wfc_s = reinterpret_cast<float*>(smem + SM_WFC);
    float*  x_s   = reinterpret_cast<float*>(smem + SM_X);

    // ---- prologue: W_hh -> fp16 table; pack bias/wih; stage x ----
    for (int i = tid; i < 256 * 64; i += NTH) {
        int n = i >> 6, k = i & 63;
        whi[n * ROWPAD + k] = __float2half_rn(W_hh[i]);
    }
    if (tid < 256) {
        int type = tid >> 6, j = tid & 63;
        int jg = j >> 3, tg = (j >> 1) & 3, col = j & 1;
        int base = (jg * 4 + tg) * 16 + col * 4 + type;
        bc_s[base]     = b_ih[tid] + b_hh[tid];
        bc_s[base + 8] = W_ih[tid];
    }
    if (tid < 64) wfc_s[tid] = W_fc[tid];
    {
        long base = (long)blockIdx.x * MT * TSTEPS;
        for (int i = tid; i < MT * TSTEPS; i += NTH) {
            long gi = base + i;
            x_s[i] = (gi < (long)B * TSTEPS) ? x[gi] : 0.0f;
        }
    }
    __syncthreads();   // only block-wide sync

    // ---- per-thread setup: warp owns rows [warp*32, warp*32+32) ----
    const int rbase = warp * 32 + gid;   // rows rbase + {0,8,16,24}
    const float bfc = b_fc[0];

    const u32 a_hi  = sb + SM_A + (u32)warp * 4608u;
    const u32 whi_b = sb + SM_WHI;
    const u32 lmoffB = (u32)((lane & 7) * (ROWPAD * 2) + (lane >> 3) * 16);
    const u32 lmoffA = (u32)((lane & 15) * (ROWPAD * 2) + (lane >> 4) * 16);

    float c[64];                 // c[mt*32 + jg*4 + p]
#pragma unroll
    for (int i = 0; i < 64; i++) c[i] = 0.0f;
    float oacc[4];
#pragma unroll
    for (int i = 0; i < 4; i++) oacc[i] = 0.0f;

#pragma unroll
    for (int s = 0; s < TSTEPS; s++) {
        float xs[4];             // xs[mt*2+half] -> row rbase + (mt*2+half)*8
#pragma unroll
        for (int q = 0; q < 4; q++)
            xs[q] = x_s[(rbase + q * 8) * TSTEPS + s];

        u32 Ahi[2][4][4];
        if (s > 0) {
#pragma unroll
            for (int mt = 0; mt < 2; mt++)
#pragma unroll
                for (int kc = 0; kc < 4; kc++)
                    ldsm4(Ahi[mt][kc],
                          a_hi + (u32)(mt * 2304 + kc * 32) + lmoffA);
        }

#pragma unroll
        for (int jg = 0; jg < 8; jg++) {
            // one B load serves both m16 tiles
            u32 bh[32];
            if (s > 0) {
#pragma unroll
                for (int ty = 0; ty < 4; ty++) {
                    u32 rb = whi_b + (u32)((ty * 64 + jg * 8) * (ROWPAD * 2)) + lmoffB;
                    ldsm4(bh + ty * 8,     rb);        // W_hi k[0,32)
                    ldsm4(bh + ty * 8 + 4, rb + 64);   // W_hi k[32,64)
                }
            }

            const float4* bc = reinterpret_cast<const float4*>(bc_s)
                               + (jg * 4 + tig) * 4;
            float4 b0 = bc[0];   // bias col0 {i,f,g,o}
            float4 b1 = bc[1];   // bias col1
            float4 w0 = bc[2];   // wih  col0
            float4 w1 = bc[3];   // wih  col1
            const int cb = jg * 8 + 2 * tig;

#pragma unroll
            for (int mt = 0; mt < 2; mt++) {
                float D[4][4];
#pragma unroll
                for (int ty = 0; ty < 4; ty++)
#pragma unroll
                    for (int p = 0; p < 4; p++) D[ty][p] = 0.0f;

                if (s > 0) {
#pragma unroll
                    for (int ty = 0; ty < 4; ty++)
#pragma unroll
                        for (int kk = 0; kk < 4; kk++)
                            mma16816(D[ty], Ahi[mt][kk], bh + ty * 8 + 2 * kk);
                }

                float hv[4];
#pragma unroll
                for (int p = 0; p < 4; p++) {
                    const float xv = xs[mt * 2 + (p >> 1)];
                    const bool hi = (p & 1);
                    const float4 bb = hi ? b1 : b0;
                    const float4 ww = hi ? w1 : w0;
                    float gI = D[0][p] + fmaf(xv, ww.x, bb.x);
                    float gF = D[1][p] + fmaf(xv, ww.y, bb.y);
                    float gG = D[2][p] + fmaf(xv, ww.z, bb.z);
                    float gO = D[3][p] + fmaf(xv, ww.w, bb.w);
                    float iv = sigf(gI);
                    float fv = sigf(gF);
                    float gv = tanh_hw(gG);
                    float ov = sigf(gO);
                    const int ci = mt * 32 + jg * 4 + p;
                    float cn = fmaf(fv, c[ci], iv * gv);
                    c[ci] = cn;
                    hv[p] = ov * tanh_hw(cn);
                }

                if (s < TSTEPS - 1) {
                    u32 off = (u32)(((mt * 16 + gid) * ROWPAD + cb) * 2);
                    sts32(a_hi + off,                  packh2(hv[0], hv[1]));
                    sts32(a_hi + off + 8 * ROWPAD * 2, packh2(hv[2], hv[3]));
                } else {
                    float2 wf = *(const float2*)(wfc_s + cb);
                    oacc[mt * 2 + 0] = fmaf(hv[0], wf.x, fmaf(hv[1], wf.y, oacc[mt * 2 + 0]));
                    oacc[mt * 2 + 1] = fmaf(hv[2], wf.x, fmaf(hv[3], wf.y, oacc[mt * 2 + 1]));
                }
            }
        }
        __syncwarp();   // h stores visible warp-wide before next ldsm
    }

    // ---- head: reduce over the 4 tig lanes sharing each row ----
#pragma unroll
    for (int q = 0; q < 4; q++) {
        float v = oacc[q];
        v += __shfl_xor_sync(0xffffffffu, v, 1);
        v += __shfl_xor_sync(0xffffffffu, v, 2);
        if (tig == 0) {
            long g = (long)blockIdx.x * MT + rbase + q * 8;
            if (g < B) out[g] = v + bfc;
        }
    }
}

extern "C" void kernel_launch(void* const* d_in, const int* in_sizes, int n_in,
                              void* d_out, int out_size) {
    const float* x    = (const float*)d_in[0];
    const float* W_ih = (const float*)d_in[1];
    const float* W_hh = (const float*)d_in[2];
    const float* b_ih = (const float*)d_in[3];
    const float* b_hh = (const float*)d_in[4];
    const float* W_fc = (const float*)d_in[5];
    const float* b_fc = (const float*)d_in[6];
    float* out = (float*)d_out;

    const int B = in_sizes[0] / TSTEPS;
    const int grid = (B + MT - 1) / MT;

    cudaFuncSetAttribute(lstm_mma_kernel,
                         cudaFuncAttributeMaxDynamicSharedMemorySize, SM_SIZE);
    lstm_mma_kernel<<<grid, NTH, SM_SIZE>>>(x, W_ih, W_hh, b_ih, b_hh,
                                            W_fc, b_fc, out, B);
}

// round 11
// speedup vs baseline: 1.0098x; 1.0098x over previous
#include <cuda_runtime.h>
#include <cuda_fp16.h>

// WaterLevelLSTM via mma.sync.m16n8k16 (f16->f32), single-term fp16 h.
// R11: operand flip. D[gate,batch] = W[gate,64] @ h[64,batch]:
//  - W = A operand, ldmatrix'd into registers ONCE (no W-LDS in time loop)
//  - gate rows permuted so each thread's D fragment holds i,f,g,o of ONE
//    hidden unit j -> c/h update entirely in registers, no gate exchange
//  - h = B operand: 32x64 fp16 tile, double-buffered in smem, 1 sync/step
//  - bias & W_ih in 8 per-thread registers (bias-LDS stream deleted)
// CTA = 32 batch rows, 256 threads, 2 CTAs/SM.

#define TSTEPS 5
#define NTH    256
#define NBATCH 32
#define HROW   72          // halves per staged row (144 B, conflict-free)

// smem byte offsets
#define SM_WST  0          // permuted W fp16 [256][72] = 36864; dead after
                           // prologue -> aliased by final-h fp32 [32][68]
#define SM_H    36864      // h fp16 double buffer: 2 x 32*144 = 9216
#define SM_XT   46080      // x transposed [5][32] floats = 640
#define SM_WFC  46720      // 64 floats
#define SM_SIZE 46976

typedef unsigned int u32;

__device__ __forceinline__ void mma16816(float* d, const u32* a, const u32* b) {
    asm volatile("mma.sync.aligned.m16n8k16.row.col.f32.f16.f16.f32 "
        "{%0,%1,%2,%3}, {%4,%5,%6,%7}, {%8,%9}, {%0,%1,%2,%3};"
        : "+f"(d[0]), "+f"(d[1]), "+f"(d[2]), "+f"(d[3])
        : "r"(a[0]), "r"(a[1]), "r"(a[2]), "r"(a[3]), "r"(b[0]), "r"(b[1]));
}
__device__ __forceinline__ void ldsm4(u32* r, u32 addr) {
    asm volatile("ldmatrix.sync.aligned.m8n8.x4.shared.b16 {%0,%1,%2,%3}, [%4];"
        : "=r"(r[0]), "=r"(r[1]), "=r"(r[2]), "=r"(r[3]) : "r"(addr));
}
__device__ __forceinline__ u32 s2u(const void* p) {
    u32 a;
    asm("{ .reg .u64 t; cvta.to.shared.u64 t, %1; cvt.u32.u64 %0, t; }"
        : "=r"(a) : "l"(p));
    return a;
}
// hardware tanh (MUFU.TANH): 1 MUFU op
__device__ __forceinline__ float tanh_hw(float x) {
    float r;
    asm("tanh.approx.f32 %0, %1;" : "=f"(r) : "f"(x));
    return r;
}
__device__ __forceinline__ float sigf(float x) {
    return fmaf(tanh_hw(0.5f * x), 0.5f, 0.5f);
}

__global__ __launch_bounds__(NTH, 2)
void lstm_mma_kernel(const float* __restrict__ x,
                     const float* __restrict__ W_ih,
                     const float* __restrict__ W_hh,
                     const float* __restrict__ b_ih,
                     const float* __restrict__ b_hh,
                     const float* __restrict__ W_fc,
                     const float* __restrict__ b_fc,
                     float* __restrict__ out,
                     int B)
{
    extern __shared__ char smem[];
    const u32 sb = s2u(smem);
    const int tid  = threadIdx.x;
    const int warp = tid >> 5;
    const int lane = tid & 31;
    const int gid  = lane >> 2;      // row group in m16 tile -> hidden unit
    const int tig  = lane & 3;       // col group -> batch cols

    __half* wst   = reinterpret_cast<__half*>(smem + SM_WST);
    float*  hf32  = reinterpret_cast<float*>(smem + SM_WST);  // alias, post-prologue
    __half* h_s   = reinterpret_cast<__half*>(smem + SM_H);   // [buf][n][HROW]
    float*  xt    = reinterpret_cast<float*>(smem + SM_XT);
    float*  wfc_s = reinterpret_cast<float*>(smem + SM_WFC);

    // ---- prologue: stage W_hh fp16 with gate-row permutation ----
    // prow(type,j) = 32*(j>>3) + 16*(type>>1) + 8*(type&1) + (j&7)
    // => warp w's 2 m16 tiles (rows 32w..32w+31) = [i(j0..7),f(j0..7)],
    //    [g(j0..7),o(j0..7)] for j in [8w, 8w+8)
    for (int i = tid; i < 256 * 64; i += NTH) {
        int n = i >> 6, k = i & 63;
        int type = n >> 6, j = n & 63;
        int prow = 32 * (j >> 3) + 16 * (type >> 1) + 8 * (type & 1) + (j & 7);
        wst[prow * HROW + k] = __float2half_rn(W_hh[i]);
    }
    if (tid < NBATCH * TSTEPS) {            // x transposed [s][n]
        int n = tid / TSTEPS, s = tid % TSTEPS;
        long gb = (long)blockIdx.x * NBATCH + n;
        xt[s * NBATCH + n] = (gb < B) ? x[gb * TSTEPS + s] : 0.0f;
    }
    if (tid < 64) wfc_s[tid] = W_fc[tid];
    __syncthreads();

    // ---- A fragments: this warp's 32 W rows, in registers forever ----
    const u32 lmA = (u32)((lane & 15) * (HROW * 2) + (lane >> 4) * 16);
    u32 A[2][4][4];
#pragma unroll
    for (int mt = 0; mt < 2; mt++)
#pragma unroll
        for (int kc = 0; kc < 4; kc++)
            ldsm4(A[mt][kc],
                  sb + SM_WST + (u32)((32 * warp + 16 * mt) * (HROW * 2) + kc * 32) + lmA);

    // ---- per-thread constants: unit j = 8*warp + gid ----
    const int j = warp * 8 + gid;
    float biasv[4], wihv[4];
#pragma unroll
    for (int t = 0; t < 4; t++) {
        biasv[t] = b_ih[t * 64 + j] + b_hh[t * 64 + j];
        wihv[t]  = W_ih[t * 64 + j];
    }

    const u32 hb0 = sb + SM_H;
    const u32 lmB = (u32)((lane & 7) * (HROW * 2) + (lane >> 3) * 16);

    float c[8];
#pragma unroll
    for (int i = 0; i < 8; i++) c[i] = 0.0f;

#pragma unroll
    for (int s = 0; s < TSTEPS; s++) {
        // ---- B fragments: h tile written last step ----
        u32 Bf[4][8];
        if (s > 0) {
            const u32 hr = hb0 + (u32)(((s & 1) ^ 1) * 4608);
#pragma unroll
            for (int ng = 0; ng < 4; ng++) {
                ldsm4(Bf[ng] + 0, hr + (u32)(ng * 8 * (HROW * 2)) + lmB);       // k[0,32)
                ldsm4(Bf[ng] + 4, hr + (u32)(ng * 8 * (HROW * 2) + 64) + lmB);  // k[32,64)
            }
        }

        float D[2][4][4];
#pragma unroll
        for (int mt = 0; mt < 2; mt++)
#pragma unroll
            for (int ng = 0; ng < 4; ng++)
#pragma unroll
                for (int p = 0; p < 4; p++) D[mt][ng][p] = 0.0f;

        if (s > 0) {
#pragma unroll
            for (int ng = 0; ng < 4; ng++)
#pragma unroll
                for (int mt = 0; mt < 2; mt++)
#pragma unroll
                    for (int kk = 0; kk < 4; kk++)
                        mma16816(D[mt][ng], A[mt][kk], Bf[ng] + 2 * kk);
        }

        // ---- epilogue: 8 units (j fixed; 8 batch cols), all in registers ----
        __half* hw際 = nullptr;  // (unused)
        __half* hw = h_s + (s & 1) * 2304;
#pragma unroll
        for (int ng = 0; ng < 4; ng++) {
            float2 xp = *(const float2*)(xt + s * NBATCH + ng * 8 + 2 * tig);
#pragma unroll
            for (int b = 0; b < 2; b++) {
                const float xv = b ? xp.y : xp.x;
                // D tile0 rows: gid -> i_j, gid+8 -> f_j; tile1: g_j, o_j
                float gI = D[0][ng][b]     + fmaf(xv, wihv[0], biasv[0]);
                float gF = D[0][ng][2 + b] + fmaf(xv, wihv[1], biasv[1]);
                float gG = D[1][ng][b]     + fmaf(xv, wihv[2], biasv[2]);
                float gO = D[1][ng][2 + b] + fmaf(xv, wihv[3], biasv[3]);
                float iv = sigf(gI);
                float fv = sigf(gF);
                float gv = tanh_hw(gG);
                float ov = sigf(gO);
                float cn = fmaf(fv, c[ng * 2 + b], iv * gv);
                c[ng * 2 + b] = cn;
                float h = ov * tanh_hw(cn);
                const int n = ng * 8 + 2 * tig + b;
                if (s < TSTEPS - 1) {
                    hw[n * HROW + j] = __float2half_rn(h);   // STS.16
                } else {
                    hf32[n * 68 + j] = h;                    // exact head input
                }
            }
        }
        __syncthreads();   // h tile complete before next step's ldsm
    }

    // ---- head: out[n] = dot(h[n], W_fc) + b_fc ----
    if (tid < NBATCH) {
        long g = (long)blockIdx.x * NBATCH + tid;
        if (g < B) {
            float acc = b_fc[0];
#pragma unroll
            for (int jj = 0; jj < 64; jj++)
                acc = fmaf(hf32[tid * 68 + jj], wfc_s[jj], acc);
            out[g] = acc;
        }
    }
}

extern "C" void kernel_launch(void* const* d_in, const int* in_sizes, int n_in,
                              void* d_out, int out_size) {
    const float* x    = (const float*)d_in[0];
    const float* W_ih = (const float*)d_in[1];
    const float* W_hh = (const float*)d_in[2];
    const float* b_ih = (const float*)d_in[3];
    const float* b_hh = (const float*)d_in[4];
    const float* W_fc = (const float*)d_in[5];
    const float* b_fc = (const float*)d_in[6];
    float* out = (float*)d_out;

    const int B = in_sizes[0] / TSTEPS;
    const int grid = (B + NBATCH - 1) / NBATCH;

    cudaFuncSetAttribute(lstm_mma_kernel,
                         cudaFuncAttributeMaxDynamicSharedMemorySize, SM_SIZE);
    lstm_mma_kernel<<<grid, NTH, SM_SIZE>>>(x, W_ih, W_hh, b_ih, b_hh,
                                            W_fc, b_fc, out, B);
}

// round 12
// speedup vs baseline: 1.3164x; 1.3036x over previous
#include <cuda_runtime.h>
#include <cuda_fp16.h>

// WaterLevelLSTM via mma.sync.m16n8k16 (f16->f32), single-term fp16 h.
// R12 = R11 operand flip + PERSISTENT CTAs.
//  D[gate,batch] = W[gate,64] @ h[64,batch]; W = A operand in registers,
//  loaded ONCE per CTA lifetime; CTA grid-strides over ~28 batch tiles.
//  Gate-row permutation gives each thread i,f,g,o of one hidden unit j.
//  h = B operand: 32x64 fp16 tile double-buffered in smem, 1 bar/step.
//  Zero-C MMA form removes D-zeroing MOVs; head uses 8-lane shfl tree.

#define TSTEPS 5
#define NTH    256
#define NBATCH 32
#define HROW   72          // halves per staged row (144 B, conflict-free)

// smem byte offsets
#define SM_WST  0          // permuted W fp16 [256][72] = 36864; dead after
                           // prologue -> aliased by final-h fp32 [32][68]
#define SM_H    36864      // h fp16 double buffer: 2 x 32*144 = 9216
#define SM_XT   46080      // x transposed [5][32] floats = 640
#define SM_WFC  46720      // 64 floats
#define SM_SIZE 46976

typedef unsigned int u32;

__device__ __forceinline__ void mma16816(float* d, const u32* a, const u32* b) {
    asm volatile("mma.sync.aligned.m16n8k16.row.col.f32.f16.f16.f32 "
        "{%0,%1,%2,%3}, {%4,%5,%6,%7}, {%8,%9}, {%0,%1,%2,%3};"
        : "+f"(d[0]), "+f"(d[1]), "+f"(d[2]), "+f"(d[3])
        : "r"(a[0]), "r"(a[1]), "r"(a[2]), "r"(a[3]), "r"(b[0]), "r"(b[1]));
}
// zero-C form: D = A*B + 0 (no explicit D zeroing needed)
__device__ __forceinline__ void mma16816_zc(float* d, const u32* a, const u32* b) {
    asm volatile("mma.sync.aligned.m16n8k16.row.col.f32.f16.f16.f32 "
        "{%0,%1,%2,%3}, {%4,%5,%6,%7}, {%8,%9}, {%10,%11,%12,%13};"
        : "=f"(d[0]), "=f"(d[1]), "=f"(d[2]), "=f"(d[3])
        : "r"(a[0]), "r"(a[1]), "r"(a[2]), "r"(a[3]), "r"(b[0]), "r"(b[1]),
          "f"(0.0f), "f"(0.0f), "f"(0.0f), "f"(0.0f));
}
__device__ __forceinline__ void ldsm4(u32* r, u32 addr) {
    asm volatile("ldmatrix.sync.aligned.m8n8.x4.shared.b16 {%0,%1,%2,%3}, [%4];"
        : "=r"(r[0]), "=r"(r[1]), "=r"(r[2]), "=r"(r[3]) : "r"(addr));
}
__device__ __forceinline__ u32 s2u(const void* p) {
    u32 a;
    asm("{ .reg .u64 t; cvta.to.shared.u64 t, %1; cvt.u32.u64 %0, t; }"
        : "=r"(a) : "l"(p));
    return a;
}
// hardware tanh (MUFU.TANH): 1 MUFU op
__device__ __forceinline__ float tanh_hw(float x) {
    float r;
    asm("tanh.approx.f32 %0, %1;" : "=f"(r) : "f"(x));
    return r;
}
__device__ __forceinline__ float sigf(float x) {
    return fmaf(tanh_hw(0.5f * x), 0.5f, 0.5f);
}

__global__ __launch_bounds__(NTH, 2)
void lstm_mma_kernel(const float* __restrict__ x,
                     const float* __restrict__ W_ih,
                     const float* __restrict__ W_hh,
                     const float* __restrict__ b_ih,
                     const float* __restrict__ b_hh,
                     const float* __restrict__ W_fc,
                     const float* __restrict__ b_fc,
                     float* __restrict__ out,
                     int B, int ntiles)
{
    extern __shared__ char smem[];
    const u32 sb = s2u(smem);
    const int tid  = threadIdx.x;
    const int warp = tid >> 5;
    const int lane = tid & 31;
    const int gid  = lane >> 2;      // row group in m16 tile -> hidden unit
    const int tig  = lane & 3;       // col group -> batch cols

    __half* wst   = reinterpret_cast<__half*>(smem + SM_WST);
    float*  hf32  = reinterpret_cast<float*>(smem + SM_WST);  // alias, post-prologue
    __half* h_s   = reinterpret_cast<__half*>(smem + SM_H);   // [buf][n][HROW]
    float*  xt    = reinterpret_cast<float*>(smem + SM_XT);
    float*  wfc_s = reinterpret_cast<float*>(smem + SM_WFC);

    // ---- one-time prologue: stage W_hh fp16 with gate-row permutation ----
    // prow(type,j) = 32*(j>>3) + 16*(type>>1) + 8*(type&1) + (j&7)
    for (int i = tid; i < 256 * 64; i += NTH) {
        int n = i >> 6, k = i & 63;
        int type = n >> 6, j = n & 63;
        int prow = 32 * (j >> 3) + 16 * (type >> 1) + 8 * (type & 1) + (j & 7);
        wst[prow * HROW + k] = __float2half_rn(W_hh[i]);
    }
    if (tid < 64) wfc_s[tid] = W_fc[tid];
    __syncthreads();

    // A fragments: this warp's 32 W rows, in registers for the whole kernel
    const u32 lmA = (u32)((lane & 15) * (HROW * 2) + (lane >> 4) * 16);
    u32 A[2][4][4];
#pragma unroll
    for (int mt = 0; mt < 2; mt++)
#pragma unroll
        for (int kc = 0; kc < 4; kc++)
            ldsm4(A[mt][kc],
                  sb + SM_WST + (u32)((32 * warp + 16 * mt) * (HROW * 2) + kc * 32) + lmA);

    // per-thread constants: unit j = 8*warp + gid
    const int j = warp * 8 + gid;
    float biasv[4], wihv[4];
#pragma unroll
    for (int t = 0; t < 4; t++) {
        biasv[t] = b_ih[t * 64 + j] + b_hh[t * 64 + j];
        wihv[t]  = W_ih[t * 64 + j];
    }
    const float bfc = b_fc[0];

    const u32 hb0 = sb + SM_H;
    const u32 lmB = (u32)((lane & 7) * (HROW * 2) + (lane >> 3) * 16);

    __syncthreads();   // all A-ldsm done before wst region is aliased by hf32

    // ================= persistent loop over batch tiles =================
    for (int tile = blockIdx.x; tile < ntiles; tile += gridDim.x) {
        // stage x transposed [s][n]
        if (tid < NBATCH * TSTEPS) {
            int n = tid / TSTEPS, s = tid % TSTEPS;
            long gb = (long)tile * NBATCH + n;
            xt[s * NBATCH + n] = (gb < B) ? x[gb * TSTEPS + s] : 0.0f;
        }
        __syncthreads();

        float c[8];
#pragma unroll
        for (int i = 0; i < 8; i++) c[i] = 0.0f;

#pragma unroll
        for (int s = 0; s < TSTEPS; s++) {
            u32 Bf[4][8];
            float D[2][4][4];
            if (s > 0) {
                const u32 hr = hb0 + (u32)(((s & 1) ^ 1) * 4608);
#pragma unroll
                for (int ng = 0; ng < 4; ng++) {
                    ldsm4(Bf[ng] + 0, hr + (u32)(ng * 8 * (HROW * 2)) + lmB);
                    ldsm4(Bf[ng] + 4, hr + (u32)(ng * 8 * (HROW * 2) + 64) + lmB);
                }
#pragma unroll
                for (int ng = 0; ng < 4; ng++)
#pragma unroll
                    for (int mt = 0; mt < 2; mt++) {
                        mma16816_zc(D[mt][ng], A[mt][0], Bf[ng] + 0);
#pragma unroll
                        for (int kk = 1; kk < 4; kk++)
                            mma16816(D[mt][ng], A[mt][kk], Bf[ng] + 2 * kk);
                    }
            }

            // epilogue: 8 units (j fixed; 8 batch cols), all in registers
            __half* hw = h_s + (s & 1) * 2304;
#pragma unroll
            for (int ng = 0; ng < 4; ng++) {
                float2 xp = *(const float2*)(xt + s * NBATCH + ng * 8 + 2 * tig);
#pragma unroll
                for (int b = 0; b < 2; b++) {
                    const float xv = b ? xp.y : xp.x;
                    float gI = fmaf(xv, wihv[0], biasv[0]);
                    float gF = fmaf(xv, wihv[1], biasv[1]);
                    float gG = fmaf(xv, wihv[2], biasv[2]);
                    float gO = fmaf(xv, wihv[3], biasv[3]);
                    if (s > 0) {
                        gI += D[0][ng][b];
                        gF += D[0][ng][2 + b];
                        gG += D[1][ng][b];
                        gO += D[1][ng][2 + b];
                    }
                    float iv = sigf(gI);
                    float fv = sigf(gF);
                    float gv = tanh_hw(gG);
                    float ov = sigf(gO);
                    float cn = fmaf(fv, c[ng * 2 + b], iv * gv);
                    c[ng * 2 + b] = cn;
                    float h = ov * tanh_hw(cn);
                    const int n = ng * 8 + 2 * tig + b;
                    if (s < TSTEPS - 1) {
                        hw[n * HROW + j] = __float2half_rn(h);   // STS.16
                    } else {
                        hf32[n * 68 + j] = h;                    // exact head input
                    }
                }
            }
            __syncthreads();   // h tile complete before next step's ldsm
        }

        // ---- head: 8 threads per batch row, shfl-tree reduce ----
        {
            const int n    = tid >> 3;       // batch row 0..31
            const int part = tid & 7;        // j-chunk
            float acc = 0.0f;
#pragma unroll
            for (int q = 0; q < 8; q++) {
                int jj = part * 8 + q;
                acc = fmaf(hf32[n * 68 + jj], wfc_s[jj], acc);
            }
            acc += __shfl_xor_sync(0xffffffffu, acc, 1);
            acc += __shfl_xor_sync(0xffffffffu, acc, 2);
            acc += __shfl_xor_sync(0xffffffffu, acc, 4);
            if (part == 0) {
                long g = (long)tile * NBATCH + n;
                if (g < B) out[g] = acc + bfc;
            }
        }
        __syncthreads();   // hf32/xt reads done before next tile overwrites
    }
}

extern "C" void kernel_launch(void* const* d_in, const int* in_sizes, int n_in,
                              void* d_out, int out_size) {
    const float* x    = (const float*)d_in[0];
    const float* W_ih = (const float*)d_in[1];
    const float* W_hh = (const float*)d_in[2];
    const float* b_ih = (const float*)d_in[3];
    const float* b_hh = (const float*)d_in[4];
    const float* W_fc = (const float*)d_in[5];
    const float* b_fc = (const float*)d_in[6];
    float* out = (float*)d_out;

    const int B = in_sizes[0] / TSTEPS;
    const int ntiles = (B + NBATCH - 1) / NBATCH;
    int grid = 296;                       // 2 CTAs x 148 SMs, persistent
    if (ntiles < grid) grid = ntiles;

    cudaFuncSetAttribute(lstm_mma_kernel,
                         cudaFuncAttributeMaxDynamicSharedMemorySize, SM_SIZE);
    lstm_mma_kernel<<<grid, NTH, SM_SIZE>>>(x, W_ih, W_hh, b_ih, b_hh,
                                            W_fc, b_fc, out, B, ntiles);
}